// round 8
// baseline (speedup 1.0000x reference)
#include <cuda_runtime.h>
#include <cuda_bf16.h>
#include <cstdint>

// time_embeddings: out[b, i] = sin/cos(time[b] * 10000^(-(i//2)/640))
// B = 65536, DIM = 1280, fp32 out. HBM-write-bound (~335.5 MB out,
// running at ~6.6 TB/s effective = ~86% of spec).
//
// Round-8: grain sweep continues (888 -> 3552 -> 7104 blocks gave
// 59.4 -> 53.2 -> 51.2 us timed, monotone). GRID = 16384: 32768 row-pairs
// / 16384 blocks = EXACTLY 2 iterations per block, perfectly uniform work.
// Data path unchanged from the round-4/7 winner: one float8 chunk per
// thread, Cody-Waite + __sincosf, st.global.cs.v8.f32, 32 regs, no smem.

#define DIM      1280
#define C8S      (DIM / 8)     // 160 float8 chunks per row
#define BLOCK    320           // 2 rows x 160 chunks per block-iteration
#define GRID     16384         // 2 row-pairs per block, exact

__global__ __launch_bounds__(BLOCK, 6)
void time_emb_kernel(const float* __restrict__ time, float* __restrict__ out, int B)
{
    const int tid = threadIdx.x;
    const int sub = tid / C8S;              // 0/1: which row of the pair
    const int c8  = tid - sub * C8S;        // 0..159: float8 chunk in the row

    // rate(p) = 10000^(-p/640) = exp2(-log2(10000)/640 * p), p = i//2
    const float C = -13.287712379549449f / 640.0f;
    const int pb = 4 * c8;                  // first pair index of this chunk
    const float r0 = exp2f(C * (float)(pb + 0));
    const float r1 = exp2f(C * (float)(pb + 1));
    const float r2 = exp2f(C * (float)(pb + 2));
    const float r3 = exp2f(C * (float)(pb + 3));

    // Cody-Waite: 2*pi = HI + LO, HI=6.28125 exact for k<=160 (angle<=1000)
    const float INV2PI = 0.15915494309189535f;
    const float HI     = 6.28125f;
    const float LO     = 1.9353071795864769e-3f;

    const int stride = 2 * GRID;            // rows consumed per grid pass
    for (int row = 2 * blockIdx.x + sub; row < B; row += stride) {
        const float t = __ldg(&time[row]);

        float a0 = t * r0, a1 = t * r1, a2 = t * r2, a3 = t * r3;

        float k0 = rintf(a0 * INV2PI), k1 = rintf(a1 * INV2PI);
        float k2 = rintf(a2 * INV2PI), k3 = rintf(a3 * INV2PI);

        float x0 = fmaf(k0, -LO, fmaf(k0, -HI, a0));
        float x1 = fmaf(k1, -LO, fmaf(k1, -HI, a1));
        float x2 = fmaf(k2, -LO, fmaf(k2, -HI, a2));
        float x3 = fmaf(k3, -LO, fmaf(k3, -HI, a3));

        float s0, c0, s1, c1, s2, c2, s3, c3;
        __sincosf(x0, &s0, &c0);
        __sincosf(x1, &s1, &c1);
        __sincosf(x2, &s2, &c2);
        __sincosf(x3, &s3, &c3);

        // even col -> sin, odd col -> cos; cols 8*c8 .. 8*c8+7 of this row
        float* p = out + (size_t)row * DIM + 8 * c8;
        asm volatile(
            "st.global.cs.v8.f32 [%0], {%1, %2, %3, %4, %5, %6, %7, %8};"
            :: "l"(p),
               "f"(s0), "f"(c0), "f"(s1), "f"(c1),
               "f"(s2), "f"(c2), "f"(s3), "f"(c3)
            : "memory");
    }
}

extern "C" void kernel_launch(void* const* d_in, const int* in_sizes, int n_in,
                              void* d_out, int out_size)
{
    const float* time = (const float*)d_in[0];
    float* out = (float*)d_out;
    const int B = in_sizes[0];

    time_emb_kernel<<<GRID, BLOCK>>>(time, out, B);
}

// round 9
// speedup vs baseline: 1.0800x; 1.0800x over previous
#include <cuda_runtime.h>
#include <cuda_bf16.h>
#include <cstdint>

// time_embeddings: out[b, i] = sin/cos(time[b] * 10000^(-(i//2)/640))
// B = 65536, DIM = 1280, fp32 out. HBM-write-bound (~335.5 MB out,
// ~6.6 TB/s effective = ~86% of spec at the current best).
//
// Round-9: grain curve is convex (888:59.4, 3552:53.2, 7104:51.2,
// 16384:55.3 us timed). GRID = 8192 probes the minimum with EXACTLY
// 4 row-pairs per block: uniform work (7104 had a 4-vs-5-pair imbalance)
// while keeping 4x prologue amortization (16384's alu/issue blowup showed
// 2x is too little). Data path unchanged from the round-7 winner:
// one float8 chunk per thread, Cody-Waite + __sincosf,
// st.global.cs.v8.f32, 32 regs, no smem.

#define DIM      1280
#define C8S      (DIM / 8)     // 160 float8 chunks per row
#define BLOCK    320           // 2 rows x 160 chunks per block-iteration
#define GRID     8192          // 32768 pairs / 8192 = exactly 4 per block

__global__ __launch_bounds__(BLOCK, 6)
void time_emb_kernel(const float* __restrict__ time, float* __restrict__ out, int B)
{
    const int tid = threadIdx.x;
    const int sub = tid / C8S;              // 0/1: which row of the pair
    const int c8  = tid - sub * C8S;        // 0..159: float8 chunk in the row

    // rate(p) = 10000^(-p/640) = exp2(-log2(10000)/640 * p), p = i//2
    const float C = -13.287712379549449f / 640.0f;
    const int pb = 4 * c8;                  // first pair index of this chunk
    const float r0 = exp2f(C * (float)(pb + 0));
    const float r1 = exp2f(C * (float)(pb + 1));
    const float r2 = exp2f(C * (float)(pb + 2));
    const float r3 = exp2f(C * (float)(pb + 3));

    // Cody-Waite: 2*pi = HI + LO, HI=6.28125 exact for k<=160 (angle<=1000)
    const float INV2PI = 0.15915494309189535f;
    const float HI     = 6.28125f;
    const float LO     = 1.9353071795864769e-3f;

    const int stride = 2 * GRID;            // rows consumed per grid pass
    for (int row = 2 * blockIdx.x + sub; row < B; row += stride) {
        const float t = __ldg(&time[row]);

        float a0 = t * r0, a1 = t * r1, a2 = t * r2, a3 = t * r3;

        float k0 = rintf(a0 * INV2PI), k1 = rintf(a1 * INV2PI);
        float k2 = rintf(a2 * INV2PI), k3 = rintf(a3 * INV2PI);

        float x0 = fmaf(k0, -LO, fmaf(k0, -HI, a0));
        float x1 = fmaf(k1, -LO, fmaf(k1, -HI, a1));
        float x2 = fmaf(k2, -LO, fmaf(k2, -HI, a2));
        float x3 = fmaf(k3, -LO, fmaf(k3, -HI, a3));

        float s0, c0, s1, c1, s2, c2, s3, c3;
        __sincosf(x0, &s0, &c0);
        __sincosf(x1, &s1, &c1);
        __sincosf(x2, &s2, &c2);
        __sincosf(x3, &s3, &c3);

        // even col -> sin, odd col -> cos; cols 8*c8 .. 8*c8+7 of this row
        float* p = out + (size_t)row * DIM + 8 * c8;
        asm volatile(
            "st.global.cs.v8.f32 [%0], {%1, %2, %3, %4, %5, %6, %7, %8};"
            :: "l"(p),
               "f"(s0), "f"(c0), "f"(s1), "f"(c1),
               "f"(s2), "f"(c2), "f"(s3), "f"(c3)
            : "memory");
    }
}

extern "C" void kernel_launch(void* const* d_in, const int* in_sizes, int n_in,
                              void* d_out, int out_size)
{
    const float* time = (const float*)d_in[0];
    float* out = (float*)d_out;
    const int B = in_sizes[0];

    time_emb_kernel<<<GRID, BLOCK>>>(time, out, B);
}